// round 9
// baseline (speedup 1.0000x reference)
#include <cuda_runtime.h>
#include <cuda_fp16.h>
#include <cstdint>

#define NUM_DST   10000
#define NUM_EDGES 600000
#define DN   100
#define DE   172
#define DTF  100
#define DOUT 128
#define KDIM (DN + DE + DTF)   // 372 = 31 lanes * 12 k

// ---------------- scratch ----------------------------------------------------
__device__ float   g_qnodes[NUM_DST * DOUT];
__device__ float   g_qbk[NUM_DST * 2];
__device__ __half2 g_Pqh[(size_t)NUM_DST * KDIM];   // [d][k] -> (head0, head1) fp16
__device__ float2  g_U[(size_t)NUM_DST * KDIM];     // [d][k] -> (head0, head1) fp32
__device__ float   g_z[NUM_DST * 2];
__device__ float   g_qbias[DOUT];
__device__ float   g_absum[2];

// ---------------- kernel 0: init + derived constants -------------------------
__global__ void init_kernel(const float* __restrict__ time_b,
                            const float* __restrict__ wq,
                            const float* __restrict__ bq,
                            const float* __restrict__ att_bias)
{
    int idx = blockIdx.x * blockDim.x + threadIdx.x;
    if (idx < NUM_DST * KDIM) g_U[idx] = make_float2(0.f, 0.f);
    if (idx < NUM_DST * 2) g_z[idx] = 0.f;
    if (idx < DOUT) {
        float acc = bq[idx];
        #pragma unroll 4
        for (int t = 0; t < DTF; t++)
            acc += cosf(time_b[t]) * wq[(DN + t) * DOUT + idx];
        g_qbias[idx] = acc;
    }
    if (idx < 2) {
        float s = 0.f;
        for (int j = 0; j < DOUT / 2; j++) s += att_bias[idx * (DOUT / 2) + j];
        g_absum[idx] = s;
    }
}

// ---------------- kernel 1: Q per dst node (4 dst / block) + Q.bk ------------
__global__ __launch_bounds__(128) void qnode_kernel(const float* __restrict__ h,
                                                    const float* __restrict__ wq,
                                                    const float* __restrict__ bk)
{
    int dbase = blockIdx.x * 4;
    int c = threadIdx.x;
    __shared__ float sh[4][DN];
    __shared__ float part[4][4];
    for (int i = c; i < 4 * DN; i += 128) {
        int dl = i / DN, k = i - dl * DN;
        sh[dl][k] = h[(size_t)(dbase + dl) * DN + k];
    }
    __syncthreads();
    float qb = g_qbias[c];
    float a[4] = {qb, qb, qb, qb};
    #pragma unroll 4
    for (int k = 0; k < DN; k++) {
        float w = wq[k * DOUT + c];
        #pragma unroll
        for (int d = 0; d < 4; d++) a[d] = fmaf(sh[d][k], w, a[d]);
    }
    #pragma unroll
    for (int d = 0; d < 4; d++)
        g_qnodes[(dbase + d) * DOUT + c] = a[d];

    float bkc = bk[c];
    float p[4];
    #pragma unroll
    for (int d = 0; d < 4; d++) p[d] = a[d] * bkc;
    #pragma unroll
    for (int off = 16; off > 0; off >>= 1)
        #pragma unroll
        for (int d = 0; d < 4; d++)
            p[d] += __shfl_xor_sync(0xffffffffu, p[d], off);
    int warp = c >> 5;
    if ((c & 31) == 0)
        #pragma unroll
        for (int d = 0; d < 4; d++) part[d][warp] = p[d];
    __syncthreads();
    if (c < 8) {
        int d = c >> 1, hh = c & 1;
        g_qbk[(dbase + d) * 2 + hh] = part[d][hh * 2] + part[d][hh * 2 + 1];
    }
}

// ---------------- kernel 1b: Pq[d,k,h] = sum_c qn[d,64h+c] * wk[k,64h+c] -----
__global__ __launch_bounds__(256) void pq_kernel(const float* __restrict__ wk)
{
    __shared__ float qs[64][129];
    __shared__ float ws[64][129];
    int dbase = blockIdx.x * 64;
    int kbase = blockIdx.y * 64;
    int tid = threadIdx.x;
    for (int i = tid; i < 64 * 128; i += 256) {
        int r = i >> 7, c = i & 127;
        int d = dbase + r;
        qs[r][c] = (d < NUM_DST) ? g_qnodes[d * DOUT + c] : 0.f;
        int k = kbase + r;
        ws[r][c] = (k < KDIM) ? wk[k * DOUT + c] : 0.f;
    }
    __syncthreads();
    int tx = tid & 15, ty = tid >> 4;
    float acc[2][4][4];
    #pragma unroll
    for (int hh = 0; hh < 2; hh++)
        #pragma unroll
        for (int i = 0; i < 4; i++)
            #pragma unroll
            for (int j = 0; j < 4; j++) acc[hh][i][j] = 0.f;

    #pragma unroll 1
    for (int hh = 0; hh < 2; hh++) {
        for (int c = 0; c < 64; c++) {
            float q[4], w[4];
            #pragma unroll
            for (int i = 0; i < 4; i++) q[i] = qs[ty * 4 + i][hh * 64 + c];
            #pragma unroll
            for (int j = 0; j < 4; j++) w[j] = ws[tx * 4 + j][hh * 64 + c];
            #pragma unroll
            for (int i = 0; i < 4; i++)
                #pragma unroll
                for (int j = 0; j < 4; j++)
                    acc[hh][i][j] = fmaf(q[i], w[j], acc[hh][i][j]);
        }
    }
    #pragma unroll
    for (int i = 0; i < 4; i++) {
        int d = dbase + ty * 4 + i;
        if (d >= NUM_DST) continue;
        #pragma unroll
        for (int j = 0; j < 4; j++) {
            int k = kbase + tx * 4 + j;
            if (k >= KDIM) continue;
            g_Pqh[(size_t)d * KDIM + k] =
                __floats2half2_rn(acc[0][i][j], acc[1][i][j]);
        }
    }
}

// ---------------- kernel 2: per-edge warp, 128-bit everything ----------------
// lane L owns k in [12L, 12L+12), L < 31. All loads/reds are 16B-aligned and
// never straddle the h/ef/time segment boundaries (all multiples of 4).
__global__ __launch_bounds__(256) void scoreU_kernel(
    const float* __restrict__ h,   const float* __restrict__ ef,
    const float* __restrict__ dt,  const int*   __restrict__ dst_idx,
    const float* __restrict__ time_w, const float* __restrict__ time_b)
{
    int e = (blockIdx.x * 256 + threadIdx.x) >> 5;
    if (e >= NUM_EDGES) return;
    int lane = threadIdx.x & 31;
    float td = dt[e];
    int d = dst_idx[e];

    float v[12];
    float2 p[12];
    float a0 = 0.f, a1 = 0.f;
    const int kb = lane * 12;
    const bool act = (lane < 31);

    if (act) {
        const float* __restrict__ hrow  = h + (size_t)(NUM_DST + e) * DN;
        const float* __restrict__ efrow = ef + (size_t)e * DE;
        // kv: 3 x 128-bit groups
        #pragma unroll
        for (int g = 0; g < 3; g++) {
            int k = kb + g * 4;
            float4 t;
            if (k < DN) {
                t = __ldg((const float4*)(hrow + k));
            } else if (k < DN + DE) {
                t = __ldg((const float4*)(efrow + (k - DN)));
            } else {
                int t0 = k - DN - DE;
                t.x = __cosf(td * time_w[t0 + 0] + time_b[t0 + 0]);
                t.y = __cosf(td * time_w[t0 + 1] + time_b[t0 + 1]);
                t.z = __cosf(td * time_w[t0 + 2] + time_b[t0 + 2]);
                t.w = __cosf(td * time_w[t0 + 3] + time_b[t0 + 3]);
            }
            v[g * 4 + 0] = t.x; v[g * 4 + 1] = t.y;
            v[g * 4 + 2] = t.z; v[g * 4 + 3] = t.w;
        }
        // Pq: 3 x 128-bit loads (4 half2 each)
        const uint4* __restrict__ pq4 =
            (const uint4*)(g_Pqh + (size_t)d * KDIM + kb);
        #pragma unroll
        for (int g = 0; g < 3; g++) {
            uint4 raw = __ldg(pq4 + g);
            p[g * 4 + 0] = __half22float2(*(__half2*)&raw.x);
            p[g * 4 + 1] = __half22float2(*(__half2*)&raw.y);
            p[g * 4 + 2] = __half22float2(*(__half2*)&raw.z);
            p[g * 4 + 3] = __half22float2(*(__half2*)&raw.w);
        }
        #pragma unroll
        for (int i = 0; i < 12; i++) {
            a0 = fmaf(v[i], p[i].x, a0);
            a1 = fmaf(v[i], p[i].y, a1);
        }
    }
    #pragma unroll
    for (int off = 16; off > 0; off >>= 1) {
        a0 += __shfl_xor_sync(0xffffffffu, a0, off);
        a1 += __shfl_xor_sync(0xffffffffu, a1, off);
    }
    float s0 = a0 + g_absum[0] + g_qbk[d * 2 + 0];
    float s1 = a1 + g_absum[1] + g_qbk[d * 2 + 1];
    s0 = s0 > 0.f ? s0 : 0.2f * s0;
    s1 = s1 > 0.f ? s1 : 0.2f * s1;
    float e0 = __expf(fminf(s0, 80.f));
    float e1 = __expf(fminf(s1, 80.f));
    if (lane == 0) {
        atomicAdd(&g_z[d * 2 + 0], e0);
        atomicAdd(&g_z[d * 2 + 1], e1);
    }
    if (act) {
        // U: 6 x red.v4 (2 k x 2 heads per op)
        float2* __restrict__ Urow = g_U + (size_t)d * KDIM + kb;
        #pragma unroll
        for (int m = 0; m < 6; m++) {
            float x0 = v[2 * m + 0] * e0;
            float y0 = v[2 * m + 0] * e1;
            float x1 = v[2 * m + 1] * e0;
            float y1 = v[2 * m + 1] * e1;
            asm volatile("red.global.add.v4.f32 [%0], {%1,%2,%3,%4};"
                         :: "l"(Urow + 2 * m), "f"(x0), "f"(y0), "f"(x1), "f"(y1)
                         : "memory");
        }
    }
}

// ---------------- kernel 3: fused agg=(U/z)@wv+bv, out GEMM, relu, LN --------
__global__ __launch_bounds__(128) void outfused_kernel(
    const float* __restrict__ h,    const float* __restrict__ wv,
    const float* __restrict__ bv,   const float* __restrict__ wout,
    const float* __restrict__ bout, const float* __restrict__ ln_g,
    const float* __restrict__ ln_b, float* __restrict__ out)
{
    int dbase = blockIdx.x * 8;
    int c = threadIdx.x;
    int hh = c >> 6;
    __shared__ float sU[8][KDIM * 2];
    __shared__ float sZ[8][2];
    __shared__ float sin[8][DOUT + DN];
    __shared__ float red1[8][4], red2[8][4];

    if (c < 16) {
        int d = c >> 1, j = c & 1;
        sZ[d][j] = g_z[(dbase + d) * 2 + j];
    }
    __syncthreads();
    for (int i = c; i < 8 * KDIM * 2; i += 128) {
        int d = i / (KDIM * 2);
        int j = i - d * (KDIM * 2);
        float z = sZ[d][j & 1];
        float u = ((const float*)(g_U + (size_t)(dbase + d) * KDIM))[j];
        sU[d][j] = (z > 0.f) ? (u / z) : 0.f;
    }
    for (int i = c; i < 8 * DN; i += 128) {
        int d = i / DN, k = i - d * DN;
        sin[d][DOUT + k] = h[(size_t)(dbase + d) * DN + k];
    }
    __syncthreads();

    float acc[8];
    #pragma unroll
    for (int d = 0; d < 8; d++) acc[d] = 0.f;
    #pragma unroll 4
    for (int k = 0; k < KDIM; k++) {
        float w = wv[k * DOUT + c];
        #pragma unroll
        for (int d = 0; d < 8; d++)
            acc[d] = fmaf(sU[d][k * 2 + hh], w, acc[d]);
    }
    float bvc = bv[c];
    #pragma unroll
    for (int d = 0; d < 8; d++)
        sin[d][c] = (sZ[d][hh] > 0.f) ? (acc[d] + bvc) : 0.f;
    __syncthreads();

    float b0 = bout[c];
    float a[8];
    #pragma unroll
    for (int d = 0; d < 8; d++) a[d] = b0;
    #pragma unroll 4
    for (int k = 0; k < DOUT + DN; k++) {
        float w = wout[k * DOUT + c];
        #pragma unroll
        for (int d = 0; d < 8; d++) a[d] = fmaf(sin[d][k], w, a[d]);
    }
    float s1[8], s2[8];
    #pragma unroll
    for (int d = 0; d < 8; d++) {
        a[d] = fmaxf(a[d], 0.f);
        s1[d] = a[d];
        s2[d] = a[d] * a[d];
    }
    #pragma unroll
    for (int off = 16; off > 0; off >>= 1) {
        #pragma unroll
        for (int d = 0; d < 8; d++) {
            s1[d] += __shfl_xor_sync(0xffffffffu, s1[d], off);
            s2[d] += __shfl_xor_sync(0xffffffffu, s2[d], off);
        }
    }
    int warp = c >> 5;
    if ((c & 31) == 0) {
        #pragma unroll
        for (int d = 0; d < 8; d++) { red1[d][warp] = s1[d]; red2[d][warp] = s2[d]; }
    }
    __syncthreads();
    #pragma unroll
    for (int d = 0; d < 8; d++) {
        float t1 = red1[d][0] + red1[d][1] + red1[d][2] + red1[d][3];
        float t2 = red2[d][0] + red2[d][1] + red2[d][2] + red2[d][3];
        float mu  = t1 * (1.f / DOUT);
        float var = t2 * (1.f / DOUT) - mu * mu;
        out[(size_t)(dbase + d) * DOUT + c] =
            (a[d] - mu) * rsqrtf(var + 1e-5f) * ln_g[c] + ln_b[c];
    }
}

// ---------------- launch -----------------------------------------------------
extern "C" void kernel_launch(void* const* d_in, const int* in_sizes, int n_in,
                              void* d_out, int out_size)
{
    int off = (n_in >= 18 && in_sizes[4] == 1) ? 1 : 0;
    const float* h        = (const float*)d_in[0];
    const float* ef       = (const float*)d_in[1];
    const float* dt       = (const float*)d_in[2];
    const int*   dst_idx  = (const int*)  d_in[3];
    const float* time_w   = (const float*)d_in[4 + off];
    const float* time_b   = (const float*)d_in[5 + off];
    const float* wq       = (const float*)d_in[6 + off];
    const float* bq       = (const float*)d_in[7 + off];
    const float* wk       = (const float*)d_in[8 + off];
    const float* bk       = (const float*)d_in[9 + off];
    const float* wv       = (const float*)d_in[10 + off];
    const float* bv       = (const float*)d_in[11 + off];
    const float* att_bias = (const float*)d_in[12 + off];
    const float* wout     = (const float*)d_in[13 + off];
    const float* bout     = (const float*)d_in[14 + off];
    const float* ln_g     = (const float*)d_in[15 + off];
    const float* ln_b     = (const float*)d_in[16 + off];
    float* out = (float*)d_out;

    init_kernel<<<(NUM_DST * KDIM + 255) / 256, 256>>>(time_b, wq, bq, att_bias);
    qnode_kernel<<<NUM_DST / 4, 128>>>(h, wq, bk);
    pq_kernel<<<dim3((NUM_DST + 63) / 64, (KDIM + 63) / 64), 256>>>(wk);
    scoreU_kernel<<<NUM_EDGES / 8, 256>>>(h, ef, dt, dst_idx, time_w, time_b);
    outfused_kernel<<<NUM_DST / 8, 128>>>(h, wv, bv, wout, bout, ln_g, ln_b, out);
}

// round 10
// speedup vs baseline: 1.3772x; 1.3772x over previous
#include <cuda_runtime.h>
#include <cuda_fp16.h>
#include <cstdint>

#define NUM_DST   10000
#define NUM_EDGES 600000
#define DN   100
#define DE   172
#define DTF  100
#define DOUT 128
#define KDIM (DN + DE + DTF)   // 372
#define NPC  6                 // k-pair chunks: k = it*64 + lane*2

// ---------------- scratch ----------------------------------------------------
__device__ float   g_qnodes[NUM_DST * DOUT];
__device__ float   g_qbk[NUM_DST * 2];
__device__ __half2 g_Pqh[(size_t)NUM_DST * KDIM];   // [d][k] -> (head0, head1) fp16
__device__ float2  g_U[(size_t)NUM_DST * KDIM];     // [d][k] -> (head0, head1) fp32
__device__ float   g_z[NUM_DST * 2];
__device__ float   g_qbias[DOUT];
__device__ float   g_absum[2];

// ---------------- kernel 0: init + derived constants -------------------------
__global__ void init_kernel(const float* __restrict__ time_b,
                            const float* __restrict__ wq,
                            const float* __restrict__ bq,
                            const float* __restrict__ att_bias)
{
    int idx = blockIdx.x * blockDim.x + threadIdx.x;
    if (idx < NUM_DST * KDIM) g_U[idx] = make_float2(0.f, 0.f);
    if (idx < NUM_DST * 2) g_z[idx] = 0.f;
    if (idx < DOUT) {
        float acc = bq[idx];
        #pragma unroll 4
        for (int t = 0; t < DTF; t++)
            acc += cosf(time_b[t]) * wq[(DN + t) * DOUT + idx];
        g_qbias[idx] = acc;
    }
    if (idx < 2) {
        float s = 0.f;
        for (int j = 0; j < DOUT / 2; j++) s += att_bias[idx * (DOUT / 2) + j];
        g_absum[idx] = s;
    }
}

// ---------------- kernel 1: Q per dst node (4 dst / block) + Q.bk ------------
__global__ __launch_bounds__(128) void qnode_kernel(const float* __restrict__ h,
                                                    const float* __restrict__ wq,
                                                    const float* __restrict__ bk)
{
    int dbase = blockIdx.x * 4;
    int c = threadIdx.x;
    __shared__ float sh[4][DN];
    __shared__ float part[4][4];
    for (int i = c; i < 4 * DN; i += 128) {
        int dl = i / DN, k = i - dl * DN;
        sh[dl][k] = h[(size_t)(dbase + dl) * DN + k];
    }
    __syncthreads();
    float qb = g_qbias[c];
    float a[4] = {qb, qb, qb, qb};
    #pragma unroll 4
    for (int k = 0; k < DN; k++) {
        float w = wq[k * DOUT + c];
        #pragma unroll
        for (int d = 0; d < 4; d++) a[d] = fmaf(sh[d][k], w, a[d]);
    }
    #pragma unroll
    for (int d = 0; d < 4; d++)
        g_qnodes[(dbase + d) * DOUT + c] = a[d];

    float bkc = bk[c];
    float p[4];
    #pragma unroll
    for (int d = 0; d < 4; d++) p[d] = a[d] * bkc;
    #pragma unroll
    for (int off = 16; off > 0; off >>= 1)
        #pragma unroll
        for (int d = 0; d < 4; d++)
            p[d] += __shfl_xor_sync(0xffffffffu, p[d], off);
    int warp = c >> 5;
    if ((c & 31) == 0)
        #pragma unroll
        for (int d = 0; d < 4; d++) part[d][warp] = p[d];
    __syncthreads();
    if (c < 8) {
        int d = c >> 1, hh = c & 1;
        g_qbk[(dbase + d) * 2 + hh] = part[d][hh * 2] + part[d][hh * 2 + 1];
    }
}

// ---------------- kernel 1b: Pq[d,k,h] = sum_c qn[d,64h+c] * wk[k,64h+c] -----
__global__ __launch_bounds__(256) void pq_kernel(const float* __restrict__ wk)
{
    __shared__ float qs[64][129];
    __shared__ float ws[64][129];
    int dbase = blockIdx.x * 64;
    int kbase = blockIdx.y * 64;
    int tid = threadIdx.x;
    for (int i = tid; i < 64 * 128; i += 256) {
        int r = i >> 7, c = i & 127;
        int d = dbase + r;
        qs[r][c] = (d < NUM_DST) ? g_qnodes[d * DOUT + c] : 0.f;
        int k = kbase + r;
        ws[r][c] = (k < KDIM) ? wk[k * DOUT + c] : 0.f;
    }
    __syncthreads();
    int tx = tid & 15, ty = tid >> 4;
    float acc[2][4][4];
    #pragma unroll
    for (int hh = 0; hh < 2; hh++)
        #pragma unroll
        for (int i = 0; i < 4; i++)
            #pragma unroll
            for (int j = 0; j < 4; j++) acc[hh][i][j] = 0.f;

    #pragma unroll 1
    for (int hh = 0; hh < 2; hh++) {
        for (int c = 0; c < 64; c++) {
            float q[4], w[4];
            #pragma unroll
            for (int i = 0; i < 4; i++) q[i] = qs[ty * 4 + i][hh * 64 + c];
            #pragma unroll
            for (int j = 0; j < 4; j++) w[j] = ws[tx * 4 + j][hh * 64 + c];
            #pragma unroll
            for (int i = 0; i < 4; i++)
                #pragma unroll
                for (int j = 0; j < 4; j++)
                    acc[hh][i][j] = fmaf(q[i], w[j], acc[hh][i][j]);
        }
    }
    #pragma unroll
    for (int i = 0; i < 4; i++) {
        int d = dbase + ty * 4 + i;
        if (d >= NUM_DST) continue;
        #pragma unroll
        for (int j = 0; j < 4; j++) {
            int k = kbase + tx * 4 + j;
            if (k >= KDIM) continue;
            g_Pqh[(size_t)d * KDIM + k] =
                __floats2half2_rn(acc[0][i][j], acc[1][i][j]);
        }
    }
}

// ---------------- kernel 2: per-edge warp, k-pair mapping --------------------
// lane L owns k = it*64 + 2L (pairs). Cross-lane stride 8B: kv/Pq LDG.64 and
// U red.v4 all fully coalesced. Pairs never straddle segment boundaries
// (100 and 272 are even); all bases 8/16B-aligned.
__global__ __launch_bounds__(256) void scoreU_kernel(
    const float* __restrict__ h,   const float* __restrict__ ef,
    const float* __restrict__ dt,  const int*   __restrict__ dst_idx,
    const float* __restrict__ time_w, const float* __restrict__ time_b)
{
    int e = (blockIdx.x * 256 + threadIdx.x) >> 5;
    if (e >= NUM_EDGES) return;
    int lane = threadIdx.x & 31;
    float td = dt[e];
    int d = dst_idx[e];
    const float* __restrict__ hrow  = h + (size_t)(NUM_DST + e) * DN;
    const float* __restrict__ efrow = ef + (size_t)e * DE;

    // kv pairs
    float2 v[NPC];
    #pragma unroll
    for (int it = 0; it < NPC; it++) {
        int k = it * 64 + lane * 2;
        float2 t = make_float2(0.f, 0.f);
        if (k < DN) {
            t = __ldg((const float2*)(hrow + k));
        } else if (k < DN + DE) {
            t = __ldg((const float2*)(efrow + (k - DN)));
        } else if (k < KDIM) {
            int t0 = k - DN - DE;
            t.x = __cosf(td * time_w[t0]     + time_b[t0]);
            t.y = __cosf(td * time_w[t0 + 1] + time_b[t0 + 1]);
        }
        v[it] = t;
    }
    // Pq pairs (2 x half2 per LDG.64)
    const __half2* __restrict__ pq = g_Pqh + (size_t)d * KDIM;
    float2 p[NPC][2];
    #pragma unroll
    for (int it = 0; it < NPC; it++) {
        int k = it * 64 + lane * 2;
        if (k < KDIM) {
            uint2 raw = __ldg((const uint2*)(pq + k));
            p[it][0] = __half22float2(*(__half2*)&raw.x);
            p[it][1] = __half22float2(*(__half2*)&raw.y);
        } else {
            p[it][0] = make_float2(0.f, 0.f);
            p[it][1] = make_float2(0.f, 0.f);
        }
    }
    float a0 = 0.f, a1 = 0.f;
    #pragma unroll
    for (int it = 0; it < NPC; it++) {
        a0 = fmaf(v[it].x, p[it][0].x, a0);
        a1 = fmaf(v[it].x, p[it][0].y, a1);
        a0 = fmaf(v[it].y, p[it][1].x, a0);
        a1 = fmaf(v[it].y, p[it][1].y, a1);
    }
    #pragma unroll
    for (int off = 16; off > 0; off >>= 1) {
        a0 += __shfl_xor_sync(0xffffffffu, a0, off);
        a1 += __shfl_xor_sync(0xffffffffu, a1, off);
    }
    float s0 = a0 + g_absum[0] + g_qbk[d * 2 + 0];
    float s1 = a1 + g_absum[1] + g_qbk[d * 2 + 1];
    s0 = s0 > 0.f ? s0 : 0.2f * s0;
    s1 = s1 > 0.f ? s1 : 0.2f * s1;
    float e0 = __expf(fminf(s0, 80.f));
    float e1 = __expf(fminf(s1, 80.f));
    if (lane == 0) {
        atomicAdd(&g_z[d * 2 + 0], e0);
        atomicAdd(&g_z[d * 2 + 1], e1);
    }
    // U: one red.v4 per pair (k,k+1 x heads 0,1) — 16B/lane, coalesced
    float2* __restrict__ Urow = g_U + (size_t)d * KDIM;
    #pragma unroll
    for (int it = 0; it < NPC; it++) {
        int k = it * 64 + lane * 2;
        if (k < KDIM) {
            float x0 = v[it].x * e0;
            float y0 = v[it].x * e1;
            float x1 = v[it].y * e0;
            float y1 = v[it].y * e1;
            asm volatile("red.global.add.v4.f32 [%0], {%1,%2,%3,%4};"
                         :: "l"(Urow + k), "f"(x0), "f"(y0), "f"(x1), "f"(y1)
                         : "memory");
        }
    }
}

// ---------------- kernel 3: fused agg=(U/z)@wv+bv, out GEMM, relu, LN --------
__global__ __launch_bounds__(128) void outfused_kernel(
    const float* __restrict__ h,    const float* __restrict__ wv,
    const float* __restrict__ bv,   const float* __restrict__ wout,
    const float* __restrict__ bout, const float* __restrict__ ln_g,
    const float* __restrict__ ln_b, float* __restrict__ out)
{
    int dbase = blockIdx.x * 8;
    int c = threadIdx.x;
    int hh = c >> 6;
    __shared__ float sU[8][KDIM * 2];
    __shared__ float sZ[8][2];
    __shared__ float sin[8][DOUT + DN];
    __shared__ float red1[8][4], red2[8][4];

    if (c < 16) {
        int d = c >> 1, j = c & 1;
        sZ[d][j] = g_z[(dbase + d) * 2 + j];
    }
    __syncthreads();
    for (int i = c; i < 8 * KDIM * 2; i += 128) {
        int d = i / (KDIM * 2);
        int j = i - d * (KDIM * 2);
        float z = sZ[d][j & 1];
        float u = ((const float*)(g_U + (size_t)(dbase + d) * KDIM))[j];
        sU[d][j] = (z > 0.f) ? (u / z) : 0.f;
    }
    for (int i = c; i < 8 * DN; i += 128) {
        int d = i / DN, k = i - d * DN;
        sin[d][DOUT + k] = h[(size_t)(dbase + d) * DN + k];
    }
    __syncthreads();

    float acc[8];
    #pragma unroll
    for (int d = 0; d < 8; d++) acc[d] = 0.f;
    #pragma unroll 4
    for (int k = 0; k < KDIM; k++) {
        float w = wv[k * DOUT + c];
        #pragma unroll
        for (int d = 0; d < 8; d++)
            acc[d] = fmaf(sU[d][k * 2 + hh], w, acc[d]);
    }
    float bvc = bv[c];
    #pragma unroll
    for (int d = 0; d < 8; d++)
        sin[d][c] = (sZ[d][hh] > 0.f) ? (acc[d] + bvc) : 0.f;
    __syncthreads();

    float b0 = bout[c];
    float a[8];
    #pragma unroll
    for (int d = 0; d < 8; d++) a[d] = b0;
    #pragma unroll 4
    for (int k = 0; k < DOUT + DN; k++) {
        float w = wout[k * DOUT + c];
        #pragma unroll
        for (int d = 0; d < 8; d++) a[d] = fmaf(sin[d][k], w, a[d]);
    }
    float s1[8], s2[8];
    #pragma unroll
    for (int d = 0; d < 8; d++) {
        a[d] = fmaxf(a[d], 0.f);
        s1[d] = a[d];
        s2[d] = a[d] * a[d];
    }
    #pragma unroll
    for (int off = 16; off > 0; off >>= 1) {
        #pragma unroll
        for (int d = 0; d < 8; d++) {
            s1[d] += __shfl_xor_sync(0xffffffffu, s1[d], off);
            s2[d] += __shfl_xor_sync(0xffffffffu, s2[d], off);
        }
    }
    int warp = c >> 5;
    if ((c & 31) == 0) {
        #pragma unroll
        for (int d = 0; d < 8; d++) { red1[d][warp] = s1[d]; red2[d][warp] = s2[d]; }
    }
    __syncthreads();
    #pragma unroll
    for (int d = 0; d < 8; d++) {
        float t1 = red1[d][0] + red1[d][1] + red1[d][2] + red1[d][3];
        float t2 = red2[d][0] + red2[d][1] + red2[d][2] + red2[d][3];
        float mu  = t1 * (1.f / DOUT);
        float var = t2 * (1.f / DOUT) - mu * mu;
        out[(size_t)(dbase + d) * DOUT + c] =
            (a[d] - mu) * rsqrtf(var + 1e-5f) * ln_g[c] + ln_b[c];
    }
}

// ---------------- launch -----------------------------------------------------
extern "C" void kernel_launch(void* const* d_in, const int* in_sizes, int n_in,
                              void* d_out, int out_size)
{
    int off = (n_in >= 18 && in_sizes[4] == 1) ? 1 : 0;
    const float* h        = (const float*)d_in[0];
    const float* ef       = (const float*)d_in[1];
    const float* dt       = (const float*)d_in[2];
    const int*   dst_idx  = (const int*)  d_in[3];
    const float* time_w   = (const float*)d_in[4 + off];
    const float* time_b   = (const float*)d_in[5 + off];
    const float* wq       = (const float*)d_in[6 + off];
    const float* bq       = (const float*)d_in[7 + off];
    const float* wk       = (const float*)d_in[8 + off];
    const float* bk       = (const float*)d_in[9 + off];
    const float* wv       = (const float*)d_in[10 + off];
    const float* bv       = (const float*)d_in[11 + off];
    const float* att_bias = (const float*)d_in[12 + off];
    const float* wout     = (const float*)d_in[13 + off];
    const float* bout     = (const float*)d_in[14 + off];
    const float* ln_g     = (const float*)d_in[15 + off];
    const float* ln_b     = (const float*)d_in[16 + off];
    float* out = (float*)d_out;

    init_kernel<<<(NUM_DST * KDIM + 255) / 256, 256>>>(time_b, wq, bq, att_bias);
    qnode_kernel<<<NUM_DST / 4, 128>>>(h, wq, bk);
    pq_kernel<<<dim3((NUM_DST + 63) / 64, (KDIM + 63) / 64), 256>>>(wk);
    scoreU_kernel<<<NUM_EDGES / 8, 256>>>(h, ef, dt, dst_idx, time_w, time_b);
    outfused_kernel<<<NUM_DST / 8, 128>>>(h, wv, bv, wout, bout, ln_g, ln_b, out);
}